// round 6
// baseline (speedup 1.0000x reference)
#include <cuda_runtime.h>
#include <cuda_bf16.h>
#include <cstdint>

// out[b,r] = sum_k Xa[b,k]*G[k,r] + C[r]
//   Xa[b,k] = x[b,k] (k<512), x[b,k-512]^2 (k>=512), x = concat(sbjs, objs)
//   G[k,r]  = mu[r,k]/sig^2 (k<512), -0.5/sig^2 (k>=512)
//   C[r]    = sum_d(-0.5*mu^2/sig^2 - log sig) - 512*LOG_SQRT_2PI + 512*prior[r]
// mma.sync m16n8k16 bf16. CTA tile 64x64, warp tile 32x32 (2x2 warps).
// K-split x4 across CTAs; fp32 partials in device scratch; deterministic
// fixed-order reduce adds partials + C (assembled from 4 precompute partials).

#define BATCH 4096
#define EMB   256
#define TWO_D 512
#define NREL  128
#define KDIM  1024
#define KSPLIT 4

#define ROWB   144              // smem row pitch bytes (64 data halves + 8 pad)
#define A_TILE (64 * ROWB)      // 9216 B
#define B_TILE (64 * ROWB)      // 9216 B

__device__ __nv_bfloat16 g_B[NREL * KDIM];            // 256 KB (L2-resident)
__device__ float g_Cpart[4 * NREL];                   // per-quarter csum
__device__ float g_partial[KSPLIT * BATCH * NREL];    // 8 MB scratch

__device__ __forceinline__ uint32_t smem_u32(const void* p) {
    uint32_t a;
    asm("{ .reg .u64 t; cvta.to.shared.u64 t, %1; cvt.u32.u64 %0, t; }"
        : "=r"(a) : "l"(p));
    return a;
}

#define LDSM4(r, addr) \
    asm volatile("ldmatrix.sync.aligned.m8n8.x4.shared.b16 {%0,%1,%2,%3}, [%4];" \
        : "=r"((r)[0]), "=r"((r)[1]), "=r"((r)[2]), "=r"((r)[3]) : "r"(addr))

__device__ __forceinline__ void mma16816(float* c, const uint32_t* a,
                                         uint32_t b0, uint32_t b1) {
    asm("mma.sync.aligned.m16n8k16.row.col.f32.bf16.bf16.f32 "
        "{%0,%1,%2,%3}, {%4,%5,%6,%7}, {%8,%9}, {%0,%1,%2,%3};"
        : "+f"(c[0]), "+f"(c[1]), "+f"(c[2]), "+f"(c[3])
        : "r"(a[0]), "r"(a[1]), "r"(a[2]), "r"(a[3]), "r"(b0), "r"(b1));
}

#define CP_ASYNC16(dst, src) \
    asm volatile("cp.async.cg.shared.global [%0], [%1], 16;" \
        :: "r"(dst), "l"(src) : "memory")
#define CP_COMMIT() asm volatile("cp.async.commit_group;" ::: "memory")
#define CP_WAIT0()  asm volatile("cp.async.wait_group 0;" ::: "memory")

// ---------------------------------------------------------------------------
// Precompute: 512 CTAs = 4 per relation, 128 threads = 1 dim each.
// Writes g_B and a per-quarter partial of the C reduction.
// ---------------------------------------------------------------------------
__global__ void __launch_bounds__(128) nb_precompute(
    const float* __restrict__ mus,
    const float* __restrict__ sigmas)
{
    const int r = blockIdx.x >> 2;
    const int q = blockIdx.x & 3;
    const int t = threadIdx.x;
    const int d = q * 128 + t;
    __shared__ float red[4];

    float mu = mus[r * TWO_D + d];
    float s  = sigmas[r * TWO_D + d];
    float inv = 1.0f / (s * s);
    g_B[r * KDIM + d]         = __float2bfloat16_rn(mu * inv);
    g_B[r * KDIM + TWO_D + d] = __float2bfloat16_rn(-0.5f * inv);

    float c = fmaf(-0.5f * mu, mu * inv, -__logf(s));
    #pragma unroll
    for (int o = 16; o > 0; o >>= 1)
        c += __shfl_xor_sync(0xffffffffu, c, o);
    if ((t & 31) == 0) red[t >> 5] = c;
    __syncthreads();
    if (t == 0)
        g_Cpart[q * NREL + r] = (red[0] + red[1]) + (red[2] + red[3]);
}

// ---------------------------------------------------------------------------
// grid = 512: bid = ks*128 + nt*64 + mt. Each CTA: BM=64 x BN=64, K=256
// (4 chunks of 64). 4 warps (2x2), warp tile 32x32.
// ---------------------------------------------------------------------------
__global__ void __launch_bounds__(128) nb_mma_split(
    const float* __restrict__ sbjs,
    const float* __restrict__ objs)
{
    __shared__ __align__(16) char smA[2 * A_TILE];
    __shared__ __align__(16) char smB[2 * B_TILE];

    const int tid  = threadIdx.x;
    const int lane = tid & 31;
    const int wid  = tid >> 5;
    const int wm   = wid & 1;          // m offset wm*32
    const int wn   = wid >> 1;         // n offset wn*32
    const int bid  = blockIdx.x;
    const int mt   = bid & 63;
    const int nt   = (bid >> 6) & 1;
    const int ks   = bid >> 7;
    const int b0   = mt * 64;
    const int n0   = nt * 64;

    const uint32_t sA = smem_u32(smA);
    const uint32_t sB = smem_u32(smB);

    float acc[8][4];                   // [mh*4+nf][frag]
    #pragma unroll
    for (int f = 0; f < 8; f++)
        #pragma unroll
        for (int i = 0; i < 4; i++) acc[f][i] = 0.0f;

    const int xrow  = tid >> 1;        // 0..63
    const int xc    = tid & 1;         // 0..1 (8 float4 each)
    const int brow  = tid >> 1;        // 0..63
    const int bseg0 = (tid & 1) * 4;

    float4 xv[8];

    auto ldgX = [&](int gc) {
        const float4* src = (const float4*)(((gc >> 2) & 1) ? objs : sbjs);
        const float4* p = src + (size_t)(b0 + xrow) * (EMB / 4)
                              + (gc & 3) * 16 + xc * 8;
        #pragma unroll
        for (int j = 0; j < 8; j++) xv[j] = p[j];
    };
    auto cpB = [&](int gc, int stage) {
        const __nv_bfloat16* gp = g_B + (size_t)(n0 + brow) * KDIM
                                      + gc * 64 + bseg0 * 8;
        uint32_t dst = sB + stage * B_TILE + brow * ROWB + bseg0 * 16;
        #pragma unroll
        for (int j = 0; j < 4; j++)
            CP_ASYNC16(dst + j * 16, gp + j * 8);
        CP_COMMIT();
    };

    ldgX(ks * 4);
    cpB(ks * 4, 0);

    const uint32_t aBase = sA + (wm * 32 + (lane & 15)) * ROWB
                              + (lane >> 4) * 16;
    const uint32_t bBase = sB + (wn * 32 + (lane & 7) + ((lane >> 4) << 3)) * ROWB
                              + ((lane >> 3) & 1) * 16;

    for (int c = 0; c < 4; c++) {
        const int gc    = ks * 4 + c;
        const int stage = c & 1;
        const bool sq   = (gc >= 8);

        // convert + STS of X chunk gc
        #pragma unroll
        for (int j = 0; j < 8; j++) {
            float4 v = xv[j];
            if (sq) { v.x *= v.x; v.y *= v.y; v.z *= v.z; v.w *= v.w; }
            __nv_bfloat16 h0 = __float2bfloat16_rn(v.x);
            __nv_bfloat16 h1 = __float2bfloat16_rn(v.y);
            __nv_bfloat16 h2 = __float2bfloat16_rn(v.z);
            __nv_bfloat16 h3 = __float2bfloat16_rn(v.w);
            uint2 hi;
            hi.x = (uint32_t)__bfloat16_as_ushort(h0)
                 | ((uint32_t)__bfloat16_as_ushort(h1) << 16);
            hi.y = (uint32_t)__bfloat16_as_ushort(h2)
                 | ((uint32_t)__bfloat16_as_ushort(h3) << 16);
            int off = xrow * ROWB + (xc * 8 + j) * 8;
            *(uint2*)(smA + stage * A_TILE + off) = hi;
        }

        CP_WAIT0();
        __syncthreads();

        if (c < 3) {
            ldgX(gc + 1);
            cpB(gc + 1, stage ^ 1);
        }

        const uint32_t aA = aBase + stage * A_TILE;
        const uint32_t bA = bBase + stage * B_TILE;

        #pragma unroll
        for (int kk = 0; kk < 4; kk++) {
            uint32_t a0[4], a1[4], br0[4], br1[4];
            LDSM4(a0, aA + kk * 32);
            LDSM4(a1, aA + 16 * ROWB + kk * 32);
            LDSM4(br0, bA + kk * 32);
            LDSM4(br1, bA + 16 * ROWB + kk * 32);
            mma16816(acc[0], a0, br0[0], br0[1]);
            mma16816(acc[1], a0, br0[2], br0[3]);
            mma16816(acc[2], a0, br1[0], br1[1]);
            mma16816(acc[3], a0, br1[2], br1[3]);
            mma16816(acc[4], a1, br0[0], br0[1]);
            mma16816(acc[5], a1, br0[2], br0[3]);
            mma16816(acc[6], a1, br1[0], br1[1]);
            mma16816(acc[7], a1, br1[2], br1[3]);
        }
    }

    // ---- epilogue: write fp32 partials ----
    float* pout = g_partial + (size_t)ks * (BATCH * NREL);
    const int rb = b0 + wm * 32 + (lane >> 2);
    #pragma unroll
    for (int mh = 0; mh < 2; mh++) {
        #pragma unroll
        for (int nf = 0; nf < 4; nf++) {
            const float* a = acc[mh * 4 + nf];
            int col = n0 + wn * 32 + nf * 8 + (lane & 3) * 2;
            int r0 = rb + mh * 16;
            *(float2*)&pout[(size_t)r0 * NREL + col]       = make_float2(a[0], a[1]);
            *(float2*)&pout[(size_t)(r0 + 8) * NREL + col] = make_float2(a[2], a[3]);
        }
    }
}

// ---------------------------------------------------------------------------
// out = sum_ks partial[ks] + C, C assembled from 4 precompute partials +
// prior. Fixed order = deterministic.
// ---------------------------------------------------------------------------
__global__ void __launch_bounds__(256) nb_reduce(
    const float* __restrict__ priors, float* __restrict__ out)
{
    const int idx = blockIdx.x * 256 + threadIdx.x;     // float4 index
    const int P   = BATCH * NREL / 4;                   // 131072
    const int rg  = idx & (NREL / 4 - 1);
    const float4* p = (const float4*)g_partial;
    float4 a = p[idx];
    float4 b = p[idx + P];
    float4 c = p[idx + 2 * P];
    float4 d = p[idx + 3 * P];
    float4 c0 = ((const float4*)g_Cpart)[rg];
    float4 c1 = ((const float4*)(g_Cpart + NREL))[rg];
    float4 c2 = ((const float4*)(g_Cpart + 2 * NREL))[rg];
    float4 c3 = ((const float4*)(g_Cpart + 3 * NREL))[rg];
    float4 pr = ((const float4*)priors)[rg];
    const float K0 = -(float)TWO_D * 0.9189385332046727f;
    float4 C;
    C.x = (c0.x + c1.x) + (c2.x + c3.x) + pr.x * (float)TWO_D + K0;
    C.y = (c0.y + c1.y) + (c2.y + c3.y) + pr.y * (float)TWO_D + K0;
    C.z = (c0.z + c1.z) + (c2.z + c3.z) + pr.z * (float)TWO_D + K0;
    C.w = (c0.w + c1.w) + (c2.w + c3.w) + pr.w * (float)TWO_D + K0;
    float4 o;
    o.x = a.x + b.x + c.x + d.x + C.x;
    o.y = a.y + b.y + c.y + d.y + C.y;
    o.z = a.z + b.z + c.z + d.z + C.z;
    o.w = a.w + b.w + c.w + d.w + C.w;
    ((float4*)out)[idx] = o;
}

extern "C" void kernel_launch(void* const* d_in, const int* in_sizes, int n_in,
                              void* d_out, int out_size)
{
    const float* sbjs   = (const float*)d_in[0];
    const float* objs   = (const float*)d_in[1];
    const float* mus    = (const float*)d_in[2];
    const float* sigmas = (const float*)d_in[3];
    const float* priors = (const float*)d_in[4];
    float* out = (float*)d_out;

    nb_precompute<<<NREL * 4, 128>>>(mus, sigmas);
    nb_mma_split<<<KSPLIT * (BATCH / 64) * (NREL / 64), 128>>>(sbjs, objs);
    nb_reduce<<<(BATCH * NREL / 4) / 256, 256>>>(priors, out);
}